// round 2
// baseline (speedup 1.0000x reference)
#include <cuda_runtime.h>
#include <math.h>

#define BSZ 4
#define DCH 256
#define HC 128
#define WC 128
#define RH 64
#define RW 64
#define RAD 3
#define S2 49
#define CIN0 52
#define HID 32
#define NPIX (HC*WC)

// scratch (static device globals; no runtime allocation)
__device__ float g_q[BSZ*NPIX*DCH];     // normalized upsampled rubin, channels-last (b,p,d)
__device__ float g_k[BSZ*NPIX*DCH];     // normalized vis, channels-last
__device__ float g_x[BSZ*CIN0*NPIX];    // conv input, planar NCHW
__device__ float g_h1[BSZ*HID*NPIX];
__device__ float g_h2[BSZ*HID*NPIX];

__device__ __forceinline__ float wsum32(float v){
#pragma unroll
    for (int o = 16; o; o >>= 1) v += __shfl_xor_sync(0xffffffffu, v, o);
    return v;
}

// ---------------- K1: bilinear upsample 64->128 (half-pixel) + L2 normalize ----
__global__ __launch_bounds__(256) void k_qprep(const float* __restrict__ rubin){
    int gw = (blockIdx.x*blockDim.x + threadIdx.x) >> 5;
    int lane = threadIdx.x & 31;
    if (gw >= BSZ*NPIX) return;
    int b = gw / NPIX, p = gw % NPIX, y = p / WC, x = p % WC;
    float sy = 0.5f*y - 0.25f, sx = 0.5f*x - 0.25f;
    int y0 = (int)floorf(sy), x0 = (int)floorf(sx);
    float fy = sy - (float)y0, fx = sx - (float)x0;
    int y0c = max(y0, 0), y1c = min(y0+1, RH-1);
    int x0c = max(x0, 0), x1c = min(x0+1, RW-1);
    float w00 = (1.f-fy)*(1.f-fx), w01 = (1.f-fy)*fx, w10 = fy*(1.f-fx), w11 = fy*fx;
    const float* base = rubin + (size_t)b*RH*RW*DCH;
    const float* t00 = base + ((size_t)(y0c*RW + x0c))*DCH + lane*8;
    const float* t01 = base + ((size_t)(y0c*RW + x1c))*DCH + lane*8;
    const float* t10 = base + ((size_t)(y1c*RW + x0c))*DCH + lane*8;
    const float* t11 = base + ((size_t)(y1c*RW + x1c))*DCH + lane*8;
    float4 a0 = *(const float4*)t00, a1 = *(const float4*)(t00+4);
    float4 b0 = *(const float4*)t01, b1 = *(const float4*)(t01+4);
    float4 c0 = *(const float4*)t10, c1 = *(const float4*)(t10+4);
    float4 d0 = *(const float4*)t11, d1 = *(const float4*)(t11+4);
    float v[8];
    v[0] = w00*a0.x + w01*b0.x + w10*c0.x + w11*d0.x;
    v[1] = w00*a0.y + w01*b0.y + w10*c0.y + w11*d0.y;
    v[2] = w00*a0.z + w01*b0.z + w10*c0.z + w11*d0.z;
    v[3] = w00*a0.w + w01*b0.w + w10*c0.w + w11*d0.w;
    v[4] = w00*a1.x + w01*b1.x + w10*c1.x + w11*d1.x;
    v[5] = w00*a1.y + w01*b1.y + w10*c1.y + w11*d1.y;
    v[6] = w00*a1.z + w01*b1.z + w10*c1.z + w11*d1.z;
    v[7] = w00*a1.w + w01*b1.w + w10*c1.w + w11*d1.w;
    float ss = 0.f;
#pragma unroll
    for (int j = 0; j < 8; j++) ss += v[j]*v[j];
    ss = wsum32(ss);
    float inv = 1.f / fmaxf(sqrtf(ss), 1e-12f);
    float* o = g_q + (size_t)gw*DCH + lane*8;
    *(float4*)o     = make_float4(v[0]*inv, v[1]*inv, v[2]*inv, v[3]*inv);
    *(float4*)(o+4) = make_float4(v[4]*inv, v[5]*inv, v[6]*inv, v[7]*inv);
}

// ---------------- K2: L2 normalize vis tokens (already 128x128) ----------------
__global__ __launch_bounds__(256) void k_kprep(const float* __restrict__ vis){
    int gw = (blockIdx.x*blockDim.x + threadIdx.x) >> 5;
    int lane = threadIdx.x & 31;
    if (gw >= BSZ*NPIX) return;
    const float* t = vis + (size_t)gw*DCH + lane*8;
    float4 a0 = *(const float4*)t, a1 = *(const float4*)(t+4);
    float ss = a0.x*a0.x + a0.y*a0.y + a0.z*a0.z + a0.w*a0.w
             + a1.x*a1.x + a1.y*a1.y + a1.z*a1.z + a1.w*a1.w;
    ss = wsum32(ss);
    float inv = 1.f / fmaxf(sqrtf(ss), 1e-12f);
    float* o = g_k + (size_t)gw*DCH + lane*8;
    *(float4*)o     = make_float4(a0.x*inv, a0.y*inv, a0.z*inv, a0.w*inv);
    *(float4*)(o+4) = make_float4(a1.x*inv, a1.y*inv, a1.z*inv, a1.w*inv);
}

// ---------------- K3: correlation volume --------------------------------------
// 4 pixels per warp, 8 lanes per pixel (32 channels each). Writes corr planar
// into g_x channels [2, 51).
__global__ __launch_bounds__(256) void k_corr(void){
    int tid = threadIdx.x;
    int lane = tid & 31;
    int g = lane >> 3;          // sub-pixel 0..3
    int l = lane & 7;           // channel group 0..7 (32 ch each)
    int P = blockIdx.x*32 + (tid >> 5)*4 + g;     // global pixel id
    int b = P >> 14, p = P & (NPIX-1);
    int y = p >> 7, x = p & (WC-1);

    // load this lane's 32 channels of q
    const float4* qp = (const float4*)(g_q + (size_t)P*DCH + l*32);
    float4 q0 = qp[0], q1 = qp[1], q2 = qp[2], q3 = qp[3];
    float4 q4 = qp[4], q5 = qp[5], q6 = qp[6], q7 = qp[7];

    const float* kb = g_k + (size_t)b*NPIX*DCH;
    float* xb = g_x + (size_t)b*CIN0*NPIX + 2*(size_t)NPIX + p;

#pragma unroll 1
    for (int dy = -RAD; dy <= RAD; dy++){
        int yy = min(max(y+dy, 0), HC-1);
        const float* krow = kb + (size_t)yy*WC*DCH;
#pragma unroll
        for (int dx = -RAD; dx <= RAD; dx++){
            int xx = min(max(x+dx, 0), WC-1);
            const float4* kv = (const float4*)(krow + (size_t)xx*DCH + l*32);
            float4 k0 = kv[0], k1 = kv[1], k2 = kv[2], k3 = kv[3];
            float4 k4 = kv[4], k5 = kv[5], k6 = kv[6], k7 = kv[7];
            float s;
            s  = q0.x*k0.x + q0.y*k0.y + q0.z*k0.z + q0.w*k0.w;
            s += q1.x*k1.x + q1.y*k1.y + q1.z*k1.z + q1.w*k1.w;
            s += q2.x*k2.x + q2.y*k2.y + q2.z*k2.z + q2.w*k2.w;
            s += q3.x*k3.x + q3.y*k3.y + q3.z*k3.z + q3.w*k3.w;
            s += q4.x*k4.x + q4.y*k4.y + q4.z*k4.z + q4.w*k4.w;
            s += q5.x*k5.x + q5.y*k5.y + q5.z*k5.z + q5.w*k5.w;
            s += q6.x*k6.x + q6.y*k6.y + q6.z*k6.z + q6.w*k6.w;
            s += q7.x*k7.x + q7.y*k7.y + q7.z*k7.z + q7.w*k7.w;
            // reduce over the 8 lanes of this pixel
            s += __shfl_xor_sync(0xffffffffu, s, 1);
            s += __shfl_xor_sync(0xffffffffu, s, 2);
            s += __shfl_xor_sync(0xffffffffu, s, 4);
            if (l == 0){
                int o = (dy+RAD)*7 + (dx+RAD);
                xb[(size_t)o*NPIX] = s;
            }
        }
    }
}

// ---------------- K4: soft-argmax over 49 corr channels ------------------------
__global__ __launch_bounds__(256) void k_sam(const float* __restrict__ log_temp,
                                             float* __restrict__ out){
    int t = blockIdx.x*256 + threadIdx.x;
    int b = t >> 14, p = t & (NPIX-1);
    const float* cp = g_x + (size_t)b*CIN0*NPIX + 2*(size_t)NPIX + p;
    float c[S2];
    float m = -1e30f;
#pragma unroll
    for (int o = 0; o < S2; o++){
        c[o] = cp[(size_t)o*NPIX];
        m = fmaxf(m, c[o]);
    }
    float it = expf(-log_temp[0]);   // 1/temp
    float s = 0.f, sy = 0.f, sx = 0.f, em = 0.f;
#pragma unroll
    for (int o = 0; o < S2; o++){
        float e = expf((c[o] - m) * it);
        s += e;
        em = fmaxf(em, e);
        sy += e * (float)(o/7 - 3);
        sx += e * (float)(o%7 - 3);
    }
    float inv = 1.f / s;
    float dyv = sy*inv, dxv = sx*inv, conf = em*inv;
    float* xb = g_x + (size_t)b*CIN0*NPIX;
    xb[p] = dyv;
    xb[(size_t)NPIX + p] = dxv;
    xb[51*(size_t)NPIX + p] = conf;
    size_t ob = (size_t)b*5*NPIX;
    out[ob + 2*(size_t)NPIX + p] = dyv;
    out[ob + 3*(size_t)NPIX + p] = dxv;
    out[ob + 4*(size_t)NPIX + p] = conf;
}

// ---------------- conv 5x5 SAME, COUT=32, exact GELU, packed f32x2 FMA ---------
// block: 32x8 output tile; thread (tx, z): 8 rows x 1 col x 4 out-channels.
// Out-channel PAIRS are packed into f32x2 so the weight float4 gives two packed
// {w_oc, w_oc+1} halves for free; input value is splatted.
template<int CIN, bool DOGELU>
__global__ __launch_bounds__(256) void k_conv32(const float* __restrict__ in,
                                                float* __restrict__ out,
                                                const float* __restrict__ wt,
                                                const float* __restrict__ bs){
    const int ICCH = 4;
    __shared__ float s_in[ICCH][12][36];
    __shared__ float s_w[ICCH][25][32];
    int tx = threadIdx.x & 31;
    int z  = threadIdx.x >> 5;
    int x0 = blockIdx.x*32, y0 = blockIdx.y*8, b = blockIdx.z;

    unsigned long long acc2[2][8];   // [oc-pair][row], f32x2 packed
#pragma unroll
    for (int i = 0; i < 2; i++)
#pragma unroll
        for (int j = 0; j < 8; j++) acc2[i][j] = 0ull;

#pragma unroll 1
    for (int cb = 0; cb < CIN; cb += ICCH){
        __syncthreads();
        for (int e = threadIdx.x; e < ICCH*12*36; e += 256){
            int icl = e / (12*36); int rem = e % (12*36);
            int ry = rem / 36, rx = rem % 36;
            int gy = y0 - 2 + ry, gx = x0 - 2 + rx;
            float val = 0.f;
            if (gy >= 0 && gy < HC && gx >= 0 && gx < WC)
                val = in[(((size_t)b*CIN + cb + icl)*HC + gy)*WC + gx];
            s_in[icl][ry][rx] = val;
        }
        for (int e = threadIdx.x; e < ICCH*25*32; e += 256){
            int icl = e / 800; int rem = e % 800;
            int tap = rem / 32, oc = rem % 32;
            s_w[icl][tap][oc] = wt[((size_t)oc*CIN + cb + icl)*25 + tap];
        }
        __syncthreads();
#pragma unroll 1
        for (int icl = 0; icl < ICCH; icl++){
#pragma unroll
            for (int kx = 0; kx < 5; kx++){
                unsigned long long sv[12];
#pragma unroll
                for (int r = 0; r < 12; r++){
                    float v = s_in[icl][r][tx+kx];
                    asm("mov.b64 %0, {%1,%1};" : "=l"(sv[r]) : "f"(v));
                }
#pragma unroll
                for (int ky = 0; ky < 5; ky++){
                    ulonglong2 w2 = *(const ulonglong2*)&s_w[icl][ky*5+kx][z*4];
#pragma unroll
                    for (int yy = 0; yy < 8; yy++){
                        asm("fma.rn.f32x2 %0, %1, %2, %0;"
                            : "+l"(acc2[0][yy]) : "l"(sv[yy+ky]), "l"(w2.x));
                        asm("fma.rn.f32x2 %0, %1, %2, %0;"
                            : "+l"(acc2[1][yy]) : "l"(sv[yy+ky]), "l"(w2.y));
                    }
                }
            }
        }
    }
#pragma unroll
    for (int j = 0; j < 2; j++){
        int oc0 = z*4 + j*2;
        float bb0 = bs[oc0], bb1 = bs[oc0+1];
#pragma unroll
        for (int yy = 0; yy < 8; yy++){
            float lo, hi;
            asm("mov.b64 {%0,%1}, %2;" : "=f"(lo), "=f"(hi) : "l"(acc2[j][yy]));
            float v0 = lo + bb0, v1 = hi + bb1;
            if (DOGELU){
                v0 = 0.5f*v0*(1.f + erff(v0*0.7071067811865476f));
                v1 = 0.5f*v1*(1.f + erff(v1*0.7071067811865476f));
            }
            out[(((size_t)b*32 + oc0  )*HC + y0 + yy)*WC + x0 + tx] = v0;
            out[(((size_t)b*32 + oc0+1)*HC + y0 + yy)*WC + x0 + tx] = v1;
        }
    }
}

// ---------------- conv2 (32->2) + compose final output -------------------------
__global__ __launch_bounds__(256) void k_conv2_final(const float* __restrict__ h,
                                                     const float* __restrict__ wt,
                                                     const float* __restrict__ bs,
                                                     float* __restrict__ out){
    const int ICCH = 8;
    __shared__ float s_in[ICCH][12][36];
    __shared__ float s_w[HID][25][2];
    int tx = threadIdx.x & 31;
    int z  = threadIdx.x >> 5;
    int x0 = blockIdx.x*32, y0 = blockIdx.y*8, b = blockIdx.z;

    for (int e = threadIdx.x; e < HID*25*2; e += 256){
        int oc = e & 1; int rem = e >> 1;
        int tap = rem % 25; int ic = rem / 25;
        s_w[ic][tap][oc] = wt[((size_t)oc*HID + ic)*25 + tap];
    }

    float a0 = 0.f, a1 = 0.f;
#pragma unroll 1
    for (int cb = 0; cb < HID; cb += ICCH){
        __syncthreads();
        for (int e = threadIdx.x; e < ICCH*12*36; e += 256){
            int icl = e / (12*36); int rem = e % (12*36);
            int ry = rem / 36, rx = rem % 36;
            int gy = y0 - 2 + ry, gx = x0 - 2 + rx;
            float val = 0.f;
            if (gy >= 0 && gy < HC && gx >= 0 && gx < WC)
                val = h[(((size_t)b*HID + cb + icl)*HC + gy)*WC + gx];
            s_in[icl][ry][rx] = val;
        }
        __syncthreads();
#pragma unroll 1
        for (int icl = 0; icl < ICCH; icl++){
            int ic = cb + icl;
#pragma unroll
            for (int ky = 0; ky < 5; ky++){
#pragma unroll
                for (int kx = 0; kx < 5; kx++){
                    float2 wv = *(const float2*)&s_w[ic][ky*5+kx][0];
                    float v = s_in[icl][z+ky][tx+kx];
                    a0 += wv.x * v;
                    a1 += wv.y * v;
                }
            }
        }
    }
    int y = y0 + z, x = x0 + tx, p = y*WC + x;
    float r0 = a0 + bs[0];   // residual for dy (channel 0)
    float r1 = a1 + bs[1];   // residual for dx (channel 1)
    size_t xb = (size_t)b*CIN0*NPIX;
    float raw_dy = g_x[xb + 0*NPIX + p];
    float raw_dx = g_x[xb + 1*NPIX + p];
    const float sky = 1.6f;  // 2048 * 0.1 / 128
    size_t ob = (size_t)b*5*NPIX;
    out[ob + 0*(size_t)NPIX + p] = (raw_dx + r1) * sky;  // dra
    out[ob + 1*(size_t)NPIX + p] = (raw_dy + r0) * sky;  // ddec
}

extern "C" void kernel_launch(void* const* d_in, const int* in_sizes, int n_in,
                              void* d_out, int out_size){
    const float* rubin = (const float*)d_in[0];
    const float* vis   = (const float*)d_in[1];
    const float* w0    = (const float*)d_in[2];
    const float* b0    = (const float*)d_in[3];
    const float* w1    = (const float*)d_in[4];
    const float* b1    = (const float*)d_in[5];
    const float* w2    = (const float*)d_in[6];
    const float* b2    = (const float*)d_in[7];
    const float* lt    = (const float*)d_in[8];
    float* out = (float*)d_out;

    float *p_x, *p_h1, *p_h2;
    cudaGetSymbolAddress((void**)&p_x,  g_x);
    cudaGetSymbolAddress((void**)&p_h1, g_h1);
    cudaGetSymbolAddress((void**)&p_h2, g_h2);

    int nwarps = BSZ*NPIX;              // 65536 warps for preps
    k_qprep<<<nwarps/8, 256>>>(rubin);
    k_kprep<<<nwarps/8, 256>>>(vis);
    k_corr <<<BSZ*NPIX/32, 256>>>();    // 2048 blocks, 4 px/warp
    k_sam  <<<BSZ*NPIX/256, 256>>>(lt, out);

    dim3 g(WC/32, HC/8, BSZ);           // (4,16,4)
    k_conv32<CIN0, true><<<g, 256>>>(p_x,  p_h1, w0, b0);
    k_conv32<HID,  true><<<g, 256>>>(p_h1, p_h2, w1, b1);
    k_conv2_final<<<g, 256>>>(p_h2, w2, b2, out);
}

// round 3
// speedup vs baseline: 2.2005x; 2.2005x over previous
#include <cuda_runtime.h>
#include <math.h>

#define BSZ 4
#define DCH 256
#define HC 128
#define WC 128
#define RH 64
#define RW 64
#define RAD 3
#define S2 49
#define CIN0 52
#define HID 32
#define NPIX (HC*WC)
#define NCHK 64            // 64 chunks of 4 channels

// scratch (static device globals; no runtime allocation)
__device__ float g_q[BSZ*NCHK*NPIX*4];   // packed [b][chunk][p][4]
__device__ float g_k[BSZ*NCHK*NPIX*4];   // packed [b][chunk][p][4]
__device__ float g_x[BSZ*CIN0*NPIX];     // conv input, planar NCHW
__device__ float g_h1[BSZ*HID*NPIX];
__device__ float g_h2[BSZ*HID*NPIX];

__device__ __forceinline__ float wsum32(float v){
#pragma unroll
    for (int o = 16; o; o >>= 1) v += __shfl_xor_sync(0xffffffffu, v, o);
    return v;
}

// ---------------- K1: bilinear upsample 64->128 (half-pixel) + L2 normalize ----
// writes packed chunk-of-4 layout
__global__ __launch_bounds__(256) void k_qprep(const float* __restrict__ rubin){
    int gw = (blockIdx.x*blockDim.x + threadIdx.x) >> 5;
    int lane = threadIdx.x & 31;
    if (gw >= BSZ*NPIX) return;
    int b = gw / NPIX, p = gw % NPIX, y = p / WC, x = p % WC;
    float sy = 0.5f*y - 0.25f, sx = 0.5f*x - 0.25f;
    int y0 = (int)floorf(sy), x0 = (int)floorf(sx);
    float fy = sy - (float)y0, fx = sx - (float)x0;
    int y0c = max(y0, 0), y1c = min(y0+1, RH-1);
    int x0c = max(x0, 0), x1c = min(x0+1, RW-1);
    float w00 = (1.f-fy)*(1.f-fx), w01 = (1.f-fy)*fx, w10 = fy*(1.f-fx), w11 = fy*fx;
    const float* base = rubin + (size_t)b*RH*RW*DCH;
    const float* t00 = base + ((size_t)(y0c*RW + x0c))*DCH + lane*8;
    const float* t01 = base + ((size_t)(y0c*RW + x1c))*DCH + lane*8;
    const float* t10 = base + ((size_t)(y1c*RW + x0c))*DCH + lane*8;
    const float* t11 = base + ((size_t)(y1c*RW + x1c))*DCH + lane*8;
    float4 a0 = *(const float4*)t00, a1 = *(const float4*)(t00+4);
    float4 b0 = *(const float4*)t01, b1 = *(const float4*)(t01+4);
    float4 c0 = *(const float4*)t10, c1 = *(const float4*)(t10+4);
    float4 d0 = *(const float4*)t11, d1 = *(const float4*)(t11+4);
    float v[8];
    v[0] = w00*a0.x + w01*b0.x + w10*c0.x + w11*d0.x;
    v[1] = w00*a0.y + w01*b0.y + w10*c0.y + w11*d0.y;
    v[2] = w00*a0.z + w01*b0.z + w10*c0.z + w11*d0.z;
    v[3] = w00*a0.w + w01*b0.w + w10*c0.w + w11*d0.w;
    v[4] = w00*a1.x + w01*b1.x + w10*c1.x + w11*d1.x;
    v[5] = w00*a1.y + w01*b1.y + w10*c1.y + w11*d1.y;
    v[6] = w00*a1.z + w01*b1.z + w10*c1.z + w11*d1.z;
    v[7] = w00*a1.w + w01*b1.w + w10*c1.w + w11*d1.w;
    float ss = 0.f;
#pragma unroll
    for (int j = 0; j < 8; j++) ss += v[j]*v[j];
    ss = wsum32(ss);
    float inv = 1.f / fmaxf(sqrtf(ss), 1e-12f);
    int c0i = lane*2;
    float4* o0 = (float4*)(g_q + (((size_t)b*NCHK + c0i    )*NPIX + p)*4);
    float4* o1 = (float4*)(g_q + (((size_t)b*NCHK + c0i + 1)*NPIX + p)*4);
    *o0 = make_float4(v[0]*inv, v[1]*inv, v[2]*inv, v[3]*inv);
    *o1 = make_float4(v[4]*inv, v[5]*inv, v[6]*inv, v[7]*inv);
}

// ---------------- K2: L2 normalize vis tokens, packed layout -------------------
__global__ __launch_bounds__(256) void k_kprep(const float* __restrict__ vis){
    int gw = (blockIdx.x*blockDim.x + threadIdx.x) >> 5;
    int lane = threadIdx.x & 31;
    if (gw >= BSZ*NPIX) return;
    int b = gw / NPIX, p = gw % NPIX;
    const float* t = vis + (size_t)gw*DCH + lane*8;
    float4 a0 = *(const float4*)t, a1 = *(const float4*)(t+4);
    float ss = a0.x*a0.x + a0.y*a0.y + a0.z*a0.z + a0.w*a0.w
             + a1.x*a1.x + a1.y*a1.y + a1.z*a1.z + a1.w*a1.w;
    ss = wsum32(ss);
    float inv = 1.f / fmaxf(sqrtf(ss), 1e-12f);
    int c0i = lane*2;
    float4* o0 = (float4*)(g_k + (((size_t)b*NCHK + c0i    )*NPIX + p)*4);
    float4* o1 = (float4*)(g_k + (((size_t)b*NCHK + c0i + 1)*NPIX + p)*4);
    *o0 = make_float4(a0.x*inv, a0.y*inv, a0.z*inv, a0.w*inv);
    *o1 = make_float4(a1.x*inv, a1.y*inv, a1.z*inv, a1.w*inv);
}

// ---------------- K3: correlation volume + fused soft-argmax -------------------
// block = 2 rows x 128 px (256 threads, thread = pixel). 49 register accums.
// Per 4-ch chunk: stage 8 clamped k rows into smem, 1 q LDG.128, then
// 49 x (1 LDS.128 + 4 FFMA). No warp reductions.
__global__ __launch_bounds__(256) void k_corr(const float* __restrict__ log_temp,
                                              float* __restrict__ out){
    __shared__ float4 s_k[8][128];
    int t = threadIdx.x;
    int b  = blockIdx.x >> 6;
    int y0 = (blockIdx.x & 63) * 2;
    int r = t >> 7, x = t & 127;
    int y = y0 + r;

    const float4* kbase = (const float4*)g_k + (size_t)b*NCHK*NPIX;
    const float4* qbase = (const float4*)g_q + (size_t)b*NCHK*NPIX;

    int rows[8];
#pragma unroll
    for (int s = 0; s < 8; s++) rows[s] = min(max(y0 - 3 + s, 0), HC-1);
    int xxc[7];
#pragma unroll
    for (int d = 0; d < 7; d++) xxc[d] = min(max(x + d - 3, 0), WC-1);

    float acc[S2];
#pragma unroll
    for (int o = 0; o < S2; o++) acc[o] = 0.f;

#pragma unroll 1
    for (int c = 0; c < NCHK; c++){
        __syncthreads();
#pragma unroll
        for (int i = 0; i < 4; i++){
            int e = t + i*256;
            int s = e >> 7, j = e & 127;
            s_k[s][j] = kbase[(size_t)c*NPIX + rows[s]*WC + j];
        }
        __syncthreads();
        float4 q4 = qbase[(size_t)c*NPIX + y*WC + x];
#pragma unroll
        for (int dy = 0; dy < 7; dy++){
            int slot = r + dy;
#pragma unroll
            for (int dx = 0; dx < 7; dx++){
                float4 k4 = s_k[slot][xxc[dx]];
                acc[dy*7+dx] += q4.x*k4.x + q4.y*k4.y + q4.z*k4.z + q4.w*k4.w;
            }
        }
    }

    int p = y*WC + x;
    float* xb = g_x + (size_t)b*CIN0*NPIX;
    // write corr channels
#pragma unroll
    for (int o = 0; o < S2; o++) xb[(size_t)(2+o)*NPIX + p] = acc[o];

    // soft-argmax
    float m = -1e30f;
#pragma unroll
    for (int o = 0; o < S2; o++) m = fmaxf(m, acc[o]);
    float it = expf(-log_temp[0]);   // 1/temp
    float ssum = 0.f, sy = 0.f, sx = 0.f, em = 0.f;
#pragma unroll
    for (int o = 0; o < S2; o++){
        float e = expf((acc[o] - m) * it);
        ssum += e;
        em = fmaxf(em, e);
        sy += e * (float)(o/7 - 3);
        sx += e * (float)(o%7 - 3);
    }
    float inv = 1.f / ssum;
    float dyv = sy*inv, dxv = sx*inv, conf = em*inv;
    xb[p] = dyv;
    xb[(size_t)NPIX + p] = dxv;
    xb[51*(size_t)NPIX + p] = conf;
    size_t ob = (size_t)b*5*NPIX;
    out[ob + 2*(size_t)NPIX + p] = dyv;
    out[ob + 3*(size_t)NPIX + p] = dxv;
    out[ob + 4*(size_t)NPIX + p] = conf;
}

// ---------------- conv 5x5 SAME, COUT=32, exact GELU, packed f32x2 FMA ---------
template<int CIN, bool DOGELU>
__global__ __launch_bounds__(256) void k_conv32(const float* __restrict__ in,
                                                float* __restrict__ out,
                                                const float* __restrict__ wt,
                                                const float* __restrict__ bs){
    const int ICCH = 4;
    __shared__ float s_in[ICCH][12][36];
    __shared__ float s_w[ICCH][25][32];
    int tx = threadIdx.x & 31;
    int z  = threadIdx.x >> 5;
    int x0 = blockIdx.x*32, y0 = blockIdx.y*8, b = blockIdx.z;

    unsigned long long acc2[2][8];   // [oc-pair][row], f32x2 packed
#pragma unroll
    for (int i = 0; i < 2; i++)
#pragma unroll
        for (int j = 0; j < 8; j++) acc2[i][j] = 0ull;

#pragma unroll 1
    for (int cb = 0; cb < CIN; cb += ICCH){
        __syncthreads();
        for (int e = threadIdx.x; e < ICCH*12*36; e += 256){
            int icl = e / (12*36); int rem = e % (12*36);
            int ry = rem / 36, rx = rem % 36;
            int gy = y0 - 2 + ry, gx = x0 - 2 + rx;
            float val = 0.f;
            if (gy >= 0 && gy < HC && gx >= 0 && gx < WC)
                val = in[(((size_t)b*CIN + cb + icl)*HC + gy)*WC + gx];
            s_in[icl][ry][rx] = val;
        }
        for (int e = threadIdx.x; e < ICCH*25*32; e += 256){
            int icl = e / 800; int rem = e % 800;
            int tap = rem / 32, oc = rem % 32;
            s_w[icl][tap][oc] = wt[((size_t)oc*CIN + cb + icl)*25 + tap];
        }
        __syncthreads();
#pragma unroll 1
        for (int icl = 0; icl < ICCH; icl++){
#pragma unroll
            for (int kx = 0; kx < 5; kx++){
                unsigned long long sv[12];
#pragma unroll
                for (int r = 0; r < 12; r++){
                    float v = s_in[icl][r][tx+kx];
                    asm("mov.b64 %0, {%1,%1};" : "=l"(sv[r]) : "f"(v));
                }
#pragma unroll
                for (int ky = 0; ky < 5; ky++){
                    ulonglong2 w2 = *(const ulonglong2*)&s_w[icl][ky*5+kx][z*4];
#pragma unroll
                    for (int yy = 0; yy < 8; yy++){
                        asm("fma.rn.f32x2 %0, %1, %2, %0;"
                            : "+l"(acc2[0][yy]) : "l"(sv[yy+ky]), "l"(w2.x));
                        asm("fma.rn.f32x2 %0, %1, %2, %0;"
                            : "+l"(acc2[1][yy]) : "l"(sv[yy+ky]), "l"(w2.y));
                    }
                }
            }
        }
    }
#pragma unroll
    for (int j = 0; j < 2; j++){
        int oc0 = z*4 + j*2;
        float bb0 = bs[oc0], bb1 = bs[oc0+1];
#pragma unroll
        for (int yy = 0; yy < 8; yy++){
            float lo, hi;
            asm("mov.b64 {%0,%1}, %2;" : "=f"(lo), "=f"(hi) : "l"(acc2[j][yy]));
            float v0 = lo + bb0, v1 = hi + bb1;
            if (DOGELU){
                v0 = 0.5f*v0*(1.f + erff(v0*0.7071067811865476f));
                v1 = 0.5f*v1*(1.f + erff(v1*0.7071067811865476f));
            }
            out[(((size_t)b*32 + oc0  )*HC + y0 + yy)*WC + x0 + tx] = v0;
            out[(((size_t)b*32 + oc0+1)*HC + y0 + yy)*WC + x0 + tx] = v1;
        }
    }
}

// ---------------- conv2 (32->2) + compose final output -------------------------
__global__ __launch_bounds__(256) void k_conv2_final(const float* __restrict__ h,
                                                     const float* __restrict__ wt,
                                                     const float* __restrict__ bs,
                                                     float* __restrict__ out){
    const int ICCH = 8;
    __shared__ float s_in[ICCH][12][36];
    __shared__ float s_w[HID][25][2];
    int tx = threadIdx.x & 31;
    int z  = threadIdx.x >> 5;
    int x0 = blockIdx.x*32, y0 = blockIdx.y*8, b = blockIdx.z;

    for (int e = threadIdx.x; e < HID*25*2; e += 256){
        int oc = e & 1; int rem = e >> 1;
        int tap = rem % 25; int ic = rem / 25;
        s_w[ic][tap][oc] = wt[((size_t)oc*HID + ic)*25 + tap];
    }

    float a0 = 0.f, a1 = 0.f;
#pragma unroll 1
    for (int cb = 0; cb < HID; cb += ICCH){
        __syncthreads();
        for (int e = threadIdx.x; e < ICCH*12*36; e += 256){
            int icl = e / (12*36); int rem = e % (12*36);
            int ry = rem / 36, rx = rem % 36;
            int gy = y0 - 2 + ry, gx = x0 - 2 + rx;
            float val = 0.f;
            if (gy >= 0 && gy < HC && gx >= 0 && gx < WC)
                val = h[(((size_t)b*HID + cb + icl)*HC + gy)*WC + gx];
            s_in[icl][ry][rx] = val;
        }
        __syncthreads();
#pragma unroll 1
        for (int icl = 0; icl < ICCH; icl++){
            int ic = cb + icl;
#pragma unroll
            for (int ky = 0; ky < 5; ky++){
#pragma unroll
                for (int kx = 0; kx < 5; kx++){
                    float2 wv = *(const float2*)&s_w[ic][ky*5+kx][0];
                    float v = s_in[icl][z+ky][tx+kx];
                    a0 += wv.x * v;
                    a1 += wv.y * v;
                }
            }
        }
    }
    int y = y0 + z, x = x0 + tx, p = y*WC + x;
    float r0 = a0 + bs[0];   // residual for dy (channel 0)
    float r1 = a1 + bs[1];   // residual for dx (channel 1)
    size_t xb = (size_t)b*CIN0*NPIX;
    float raw_dy = g_x[xb + 0*NPIX + p];
    float raw_dx = g_x[xb + 1*NPIX + p];
    const float sky = 1.6f;  // 2048 * 0.1 / 128
    size_t ob = (size_t)b*5*NPIX;
    out[ob + 0*(size_t)NPIX + p] = (raw_dx + r1) * sky;  // dra
    out[ob + 1*(size_t)NPIX + p] = (raw_dy + r0) * sky;  // ddec
}

extern "C" void kernel_launch(void* const* d_in, const int* in_sizes, int n_in,
                              void* d_out, int out_size){
    const float* rubin = (const float*)d_in[0];
    const float* vis   = (const float*)d_in[1];
    const float* w0    = (const float*)d_in[2];
    const float* b0    = (const float*)d_in[3];
    const float* w1    = (const float*)d_in[4];
    const float* b1    = (const float*)d_in[5];
    const float* w2    = (const float*)d_in[6];
    const float* b2    = (const float*)d_in[7];
    const float* lt    = (const float*)d_in[8];
    float* out = (float*)d_out;

    float *p_x, *p_h1, *p_h2;
    cudaGetSymbolAddress((void**)&p_x,  g_x);
    cudaGetSymbolAddress((void**)&p_h1, g_h1);
    cudaGetSymbolAddress((void**)&p_h2, g_h2);

    int nwarps = BSZ*NPIX;              // 65536 warps for preps
    k_qprep<<<nwarps/8, 256>>>(rubin);
    k_kprep<<<nwarps/8, 256>>>(vis);
    k_corr <<<BSZ*64, 256>>>(lt, out);  // 256 blocks: 2 rows x 128 px each

    dim3 g(WC/32, HC/8, BSZ);           // (4,16,4)
    k_conv32<CIN0, true><<<g, 256>>>(p_x,  p_h1, w0, b0);
    k_conv32<HID,  true><<<g, 256>>>(p_h1, p_h2, w1, b1);
    k_conv2_final<<<g, 256>>>(p_h2, w2, b2, out);
}